// round 5
// baseline (speedup 1.0000x reference)
#include <cuda_runtime.h>

// Problem constants (B=1, H=32, Q=1024, S=4096, D=128)
#define SEQ      4096
#define ROWS     32768      // B*H*Q rows of attn_weights
#define START    4
#define HEAVY    409        // int(4096*0.1)
#define RSTART   3687       // 4096 - min(409,512)
#define NCAND    3683       // RSTART - START
#define NKEEP    822        // 4 + 409 + 409
#define HEADS    32
#define NBLK     148        // one exact wave, all co-resident
#define NTHR     1024
#define ICH      25         // candidates per block in rank phase (148*25>=3683)
#define NFIX     413        // START + recent rows (attention-independent)
#define TOTAL_F  (2*HEADS*NFIX*32)    // fixed-gather float4 count  = 845824
#define TOTAL_H  (2*HEADS*HEAVY*32)   // heavy-gather float4 count  = 837632
#define FCHUNK   4096                 // fixed-gather work-steal chunk (float4)
#define NFCHUNK  ((TOTAL_F + FCHUNK - 1) / FCHUNK)

// Scratch. g_sums is atomically accumulated so it MUST be zero at entry:
// the epilogue's last block re-zeroes it (consumers all done by then).
// Barrier counters / tickets likewise reset inside protected regions.
__device__ double g_sums[SEQ];
__device__ int    g_rank[NCAND];
__device__ int    g_cnt[2];
__device__ int    g_tick;
__device__ int    g_done;

// Software grid barrier: all NBLK blocks are co-resident (grid == one wave).
__device__ __forceinline__ void grid_bar(int idx) {
    __syncthreads();
    if (threadIdx.x == 0) {
        __threadfence();
        atomicAdd(&g_cnt[idx], 1);
        while (*(volatile int*)&g_cnt[idx] < NBLK) { }
        __threadfence();
    }
    __syncthreads();
}

__global__ void __launch_bounds__(NTHR, 1)
k_fused(const float4* __restrict__ keys,
        const float4* __restrict__ vals,
        const float*  __restrict__ attn,
        float4* __restrict__ out) {
    __shared__ unsigned long long sj[NCAND];   // rank phase: candidate sums
    __shared__ int s_keep[HEAVY];              // build phase: heavy src idxs
    __shared__ int warpsum[32];
    __shared__ int s_tick;

    const int t = threadIdx.x;
    const int b = blockIdx.x;

    // ================= Phase A: column sums (512 MB stream) ================
    // Rows strided across blocks (b, b+148, ...) for homogeneous per-block
    // cost -> minimal spread at the grid barrier. Thread t owns columns
    // [4t,4t+4) via float4; 8 front-batched LDG.128 (MLP=8); __ldcs.
    // fp32 over 32 rows flushed into fp64 -> mean accurate to ~1e-8 rel
    // (top-k boundary gap ~1e-5). fp64 atomicAdd tail (~1e-13 noise).
    {
        const float4* __restrict__ w4 = (const float4*)attn + t;
        double a0 = 0, a1 = 0, a2 = 0, a3 = 0;
        float  c0 = 0, c1 = 0, c2 = 0, c3 = 0;
        int row = b, grp = 0;
        for (; row + 7 * NBLK < ROWS; row += 8 * NBLK) {
            float4 v[8];
            #pragma unroll
            for (int k = 0; k < 8; k++)
                v[k] = __ldcs(&w4[(size_t)(row + k * NBLK) * 1024]);
            float s0x = (v[0].x + v[1].x) + (v[2].x + v[3].x);
            float s1x = (v[4].x + v[5].x) + (v[6].x + v[7].x);
            float s0y = (v[0].y + v[1].y) + (v[2].y + v[3].y);
            float s1y = (v[4].y + v[5].y) + (v[6].y + v[7].y);
            float s0z = (v[0].z + v[1].z) + (v[2].z + v[3].z);
            float s1z = (v[4].z + v[5].z) + (v[6].z + v[7].z);
            float s0w = (v[0].w + v[1].w) + (v[2].w + v[3].w);
            float s1w = (v[4].w + v[5].w) + (v[6].w + v[7].w);
            c0 += s0x + s1x;  c1 += s0y + s1y;
            c2 += s0z + s1z;  c3 += s0w + s1w;
            if (++grp == 4) {
                a0 += c0; a1 += c1; a2 += c2; a3 += c3;
                c0 = c1 = c2 = c3 = 0.f; grp = 0;
            }
        }
        for (; row < ROWS; row += NBLK) {
            float4 v = __ldcs(&w4[(size_t)row * 1024]);
            c0 += v.x; c1 += v.y; c2 += v.z; c3 += v.w;
        }
        a0 += c0; a1 += c1; a2 += c2; a3 += c3;
        int s = 4 * t;
        atomicAdd(&g_sums[s + 0], a0);
        atomicAdd(&g_sums[s + 1], a1);
        atomicAdd(&g_sums[s + 2], a2);
        atomicAdd(&g_sums[s + 3], a3);
    }

    // ---- Phase A': fixed gather (sinks + recent), WORK-STOLEN -------------
    // Early-finishing blocks absorb this 27 MB; the slowest colsum block
    // grabs nothing, so the barrier fires as soon as colsum itself is done.
    for (;;) {
        if (t == 0) s_tick = atomicAdd(&g_tick, 1);
        __syncthreads();
        int chunk = s_tick;
        __syncthreads();
        if (chunk >= NFCHUNK) break;
        int v0 = chunk * FCHUNK;
        int vend = min(v0 + FCHUNK, TOTAL_F);
        for (int v = v0 + t; v < vend; v += NTHR) {
            int d4  = v & 31;
            int row = v >> 5;
            int tensor = row / (HEADS * NFIX);
            int rem = row - tensor * (HEADS * NFIX);
            int h   = rem / NFIX;
            int p   = rem - h * NFIX;                 // 0..412
            int r   = (p < START) ? p : p + HEAVY;    // output row (keep order)
            int s   = (p < START) ? p : (RSTART + p - START);
            const float4* __restrict__ src = tensor ? vals : keys;
            out[(((size_t)(tensor * HEADS + h) * NKEEP + r) << 5) + d4] =
                __ldcs(&src[(((size_t)h * SEQ + s) << 5) + d4]);
        }
    }

    grid_bar(0);

    // ================= Phase B: rank via pairwise count ====================
    // Positive doubles -> u64 bit order isomorphic. Tie-break (equal value,
    // lower index wins) matches jax.lax.top_k. Block owns 25 candidates,
    // one warp per candidate, no atomics.
    for (int k = t; k < NCAND; k += NTHR)
        sj[k] = __double_as_longlong(__ldcg(&g_sums[START + k]));
    __syncthreads();
    {
        const int w = t >> 5, lane = t & 31;
        if (w < ICH) {
            int i = b * ICH + w;
            if (i < NCAND) {
                unsigned long long vi = sj[i];
                int cnt = 0;
                for (int j = lane; j < NCAND; j += 32) {
                    unsigned long long vj = sj[j];
                    if (vj > vi || (vj == vi && j < i)) cnt++;
                }
                #pragma unroll
                for (int o = 16; o; o >>= 1)
                    cnt += __shfl_down_sync(0xFFFFFFFFu, cnt, o);
                if (lane == 0) g_rank[i] = cnt;
            }
        }
    }

    grid_bar(1);
    if (b == 0 && t == 0) g_cnt[0] = 0;   // all blocks past barrier 0

    // ================= Phase C: build heavy keep list (redundant/block) ====
    {
        int f[4], loc = 0;
        int base = 4 * t;
        #pragma unroll
        for (int k = 0; k < 4; k++) {
            int c = base + k;
            f[k] = (c < NCAND && __ldcg(&g_rank[c]) < HEAVY) ? 1 : 0;
            loc += f[k];
        }
        int lane = t & 31, w = t >> 5;
        int v = loc;
        #pragma unroll
        for (int o = 1; o < 32; o <<= 1) {
            int n = __shfl_up_sync(0xFFFFFFFFu, v, o);
            if (lane >= o) v += n;
        }
        if (lane == 31) warpsum[w] = v;
        __syncthreads();
        if (w == 0) {
            int s = warpsum[lane];
            #pragma unroll
            for (int o = 1; o < 32; o <<= 1) {
                int n = __shfl_up_sync(0xFFFFFFFFu, s, o);
                if (lane >= o) s += n;
            }
            warpsum[lane] = s;
        }
        __syncthreads();
        int pos = v - loc + (w > 0 ? warpsum[w - 1] : 0);
        #pragma unroll
        for (int k = 0; k < 4; k++) {
            if (f[k]) { s_keep[pos] = START + base + k; pos++; }
        }
    }
    __syncthreads();

    // ================= Phase D: heavy-row gather ===========================
    for (int v = b * NTHR + t; v < TOTAL_H; v += NBLK * NTHR) {
        int d4  = v & 31;
        int row = v >> 5;
        int tensor = row / (HEADS * HEAVY);
        int rem = row - tensor * (HEADS * HEAVY);
        int h   = rem / HEAVY;
        int q   = rem - h * HEAVY;                // heavy slot 0..408
        int s   = s_keep[q];
        const float4* __restrict__ src = tensor ? vals : keys;
        out[(((size_t)(tensor * HEADS + h) * NKEEP + (START + q)) << 5) + d4] =
            __ldcs(&src[(((size_t)h * SEQ + s) << 5) + d4]);
    }

    // ---- epilogue: last block resets scratch for the next call ------------
    __syncthreads();
    if (t == 0 && atomicAdd(&g_done, 1) == NBLK - 1) {
        for (int i = 0; i < SEQ; i++) g_sums[i] = 0.0;
        g_cnt[1] = 0;
        g_tick   = 0;
        g_done   = 0;
    }
}

extern "C" void kernel_launch(void* const* d_in, const int* in_sizes, int n_in,
                              void* d_out, int out_size) {
    const float* keys = (const float*)d_in[0];   // (1,32,4096,128)
    const float* vals = (const float*)d_in[1];   // (1,32,4096,128)
    const float* attn = (const float*)d_in[2];   // (1,32,1024,4096)
    float* out = (float*)d_out;                  // 2*32*822*128 f32

    k_fused<<<NBLK, NTHR>>>((const float4*)keys, (const float4*)vals,
                            attn, (float4*)out);
}

// round 6
// speedup vs baseline: 1.1573x; 1.1573x over previous
#include <cuda_runtime.h>

// Problem constants (B=1, H=32, Q=1024, S=4096, D=128)
#define SEQ      4096
#define ROWS     32768      // B*H*Q rows of attn_weights
#define START    4
#define HEAVY    409        // int(4096*0.1)
#define RSTART   3687       // 4096 - min(409,512)
#define NCAND    3683       // RSTART - START
#define NKEEP    822        // 4 + 409 + 409
#define HEADS    32
#define NBLK     148        // one exact wave, all co-resident
#define NTHR     1024
#define ICH      25         // candidates per block in rank phase (148*25>=3683)
#define TOTAL_G  (2*HEADS*NKEEP*32)   // full gather float4 count = 1,683,456

// Scratch. g_sums is atomically accumulated so it MUST be zero at entry:
// the tail kernel's last block re-zeroes it (all consumers done by then).
__device__ double g_sums[SEQ];
__device__ int    g_rank[NCAND];
__device__ int    g_cnt;      // tail grid barrier
__device__ int    g_done;     // tail epilogue counter

// ================= Kernel 1: column sums (512 MB PURE READ stream) =========
// 148 blocks, contiguous row range each (measured 81.6us @ 83.6% DRAM).
// Thread t owns columns [4t,4t+4) via float4; 8 front-batched LDG.128
// (MLP=8); __ldcs (no reuse). fp32 over 32 rows flushed into fp64 keeps the
// mean accurate to ~1e-8 rel (top-k boundary gap ~1e-5); fp64 atomicAdd
// ordering noise ~1e-13 — selection identical to reference (rel_err 0.0).
__global__ void __launch_bounds__(NTHR, 1) k_colsum(const float* __restrict__ w) {
    const int t = threadIdx.x;
    const int b = blockIdx.x;
    const int r0 = (int)((long long)ROWS * b / NBLK);
    const int r1 = (int)((long long)ROWS * (b + 1) / NBLK);
    const float4* __restrict__ w4 = (const float4*)w + t;
    double a0 = 0, a1 = 0, a2 = 0, a3 = 0;
    float  c0 = 0, c1 = 0, c2 = 0, c3 = 0;
    int row = r0, grp = 0;
    for (; row + 8 <= r1; row += 8) {
        float4 v[8];
        #pragma unroll
        for (int k = 0; k < 8; k++)
            v[k] = __ldcs(&w4[(size_t)(row + k) * 1024]);
        float s0x = (v[0].x + v[1].x) + (v[2].x + v[3].x);
        float s1x = (v[4].x + v[5].x) + (v[6].x + v[7].x);
        float s0y = (v[0].y + v[1].y) + (v[2].y + v[3].y);
        float s1y = (v[4].y + v[5].y) + (v[6].y + v[7].y);
        float s0z = (v[0].z + v[1].z) + (v[2].z + v[3].z);
        float s1z = (v[4].z + v[5].z) + (v[6].z + v[7].z);
        float s0w = (v[0].w + v[1].w) + (v[2].w + v[3].w);
        float s1w = (v[4].w + v[5].w) + (v[6].w + v[7].w);
        c0 += s0x + s1x;  c1 += s0y + s1y;
        c2 += s0z + s1z;  c3 += s0w + s1w;
        if (++grp == 4) {                 // flush every 32 rows
            a0 += c0; a1 += c1; a2 += c2; a3 += c3;
            c0 = c1 = c2 = c3 = 0.f; grp = 0;
        }
    }
    for (; row < r1; row++) {
        float4 v = __ldcs(&w4[(size_t)row * 1024]);
        c0 += v.x; c1 += v.y; c2 += v.z; c3 += v.w;
    }
    a0 += c0; a1 += c1; a2 += c2; a3 += c3;
    int s = 4 * t;
    atomicAdd(&g_sums[s + 0], a0);
    atomicAdd(&g_sums[s + 1], a1);
    atomicAdd(&g_sums[s + 2], a2);
    atomicAdd(&g_sums[s + 3], a3);
}

// ================= Kernel 2: rank -> barrier -> build -> gather ============
__global__ void __launch_bounds__(NTHR, 1)
k_tail(const float4* __restrict__ keys,
       const float4* __restrict__ vals,
       float4* __restrict__ out) {
    __shared__ unsigned long long sj[NCAND];   // all candidate sums
    __shared__ int s_keep[NKEEP];              // full sorted keep list
    __shared__ int warpsum[32];

    const int t = threadIdx.x;
    const int b = blockIdx.x;
    const int lane = t & 31, w = t >> 5;

    // ---- Phase B: rank via pairwise count (no atomics) --------------------
    // Positive doubles -> u64 bit order isomorphic. Tie-break (equal value,
    // lower index wins) matches jax.lax.top_k. Block owns 25 candidates,
    // one warp per candidate.
    for (int k = t; k < NCAND; k += NTHR)
        sj[k] = __double_as_longlong(__ldcg(&g_sums[START + k]));
    __syncthreads();
    if (w < ICH) {
        int i = b * ICH + w;
        if (i < NCAND) {
            unsigned long long vi = sj[i];
            int cnt = 0;
            for (int j = lane; j < NCAND; j += 32) {
                unsigned long long vj = sj[j];
                if (vj > vi || (vj == vi && j < i)) cnt++;
            }
            #pragma unroll
            for (int o = 16; o; o >>= 1)
                cnt += __shfl_down_sync(0xFFFFFFFFu, cnt, o);
            if (lane == 0) g_rank[i] = cnt;
        }
    }

    // ---- grid barrier (all 148 blocks co-resident) ------------------------
    __syncthreads();
    if (t == 0) {
        __threadfence();
        atomicAdd(&g_cnt, 1);
        while (*(volatile int*)&g_cnt < NBLK) { }
        __threadfence();
    }
    __syncthreads();

    // ---- Phase C: build full sorted keep list (redundant per block) -------
    // keep = [0..3] ++ heavy(sorted asc, all in (4,3687)) ++ [3687..4095]
    // -> concatenation is already globally sorted.
    {
        int f[4], loc = 0;
        int base = 4 * t;
        #pragma unroll
        for (int k = 0; k < 4; k++) {
            int c = base + k;
            f[k] = (c < NCAND && __ldcg(&g_rank[c]) < HEAVY) ? 1 : 0;
            loc += f[k];
        }
        int v = loc;
        #pragma unroll
        for (int o = 1; o < 32; o <<= 1) {
            int n = __shfl_up_sync(0xFFFFFFFFu, v, o);
            if (lane >= o) v += n;
        }
        if (lane == 31) warpsum[w] = v;
        __syncthreads();
        if (w == 0) {
            int s = warpsum[lane];
            #pragma unroll
            for (int o = 1; o < 32; o <<= 1) {
                int n = __shfl_up_sync(0xFFFFFFFFu, s, o);
                if (lane >= o) s += n;
            }
            warpsum[lane] = s;
        }
        __syncthreads();
        int pos = START + v - loc + (w > 0 ? warpsum[w - 1] : 0);
        #pragma unroll
        for (int k = 0; k < 4; k++) {
            if (f[k]) { s_keep[pos] = START + base + k; pos++; }
        }
        if (t < START) s_keep[t] = t;
        if (t < SEQ - RSTART) s_keep[START + HEAVY + t] = RSTART + t;
    }
    __syncthreads();

    // ---- Phase D: full gather (54 MB), one wave, unroll-4 for MLP ---------
    {
        const int stride = NBLK * NTHR;         // 151552
        int v = b * NTHR + t;
        for (; v + 3 * stride < TOTAL_G; v += 4 * stride) {
            float4 d[4];
            size_t oidx[4];
            #pragma unroll
            for (int k = 0; k < 4; k++) {
                int vv  = v + k * stride;
                int d4  = vv & 31;
                int row = vv >> 5;
                int tensor = row / (HEADS * NKEEP);
                int rem = row - tensor * (HEADS * NKEEP);
                int h   = rem / NKEEP;
                int r   = rem - h * NKEEP;
                int s   = s_keep[r];
                const float4* __restrict__ src = tensor ? vals : keys;
                d[k] = __ldcs(&src[(((size_t)h * SEQ + s) << 5) + d4]);
                oidx[k] = vv;
            }
            #pragma unroll
            for (int k = 0; k < 4; k++) out[oidx[k]] = d[k];
        }
        for (; v < TOTAL_G; v += stride) {
            int d4  = v & 31;
            int row = v >> 5;
            int tensor = row / (HEADS * NKEEP);
            int rem = row - tensor * (HEADS * NKEEP);
            int h   = rem / NKEEP;
            int r   = rem - h * NKEEP;
            int s   = s_keep[r];
            const float4* __restrict__ src = tensor ? vals : keys;
            out[v] = __ldcs(&src[(((size_t)h * SEQ + s) << 5) + d4]);
        }
    }

    // ---- epilogue: last block resets scratch for the next call ------------
    __syncthreads();
    __shared__ int s_last;
    if (t == 0) {
        __threadfence();
        s_last = (atomicAdd(&g_done, 1) == NBLK - 1) ? 1 : 0;
    }
    __syncthreads();
    if (s_last) {
        for (int i = t; i < SEQ; i += NTHR) g_sums[i] = 0.0;
        if (t == 0) { g_cnt = 0; g_done = 0; }
    }
}

extern "C" void kernel_launch(void* const* d_in, const int* in_sizes, int n_in,
                              void* d_out, int out_size) {
    const float* keys = (const float*)d_in[0];   // (1,32,4096,128)
    const float* vals = (const float*)d_in[1];   // (1,32,4096,128)
    const float* attn = (const float*)d_in[2];   // (1,32,1024,4096)
    float* out = (float*)d_out;                  // 2*32*822*128 f32

    k_colsum<<<NBLK, NTHR>>>(attn);
    k_tail<<<NBLK, NTHR>>>((const float4*)keys, (const float4*)vals,
                           (float4*)out);
}